// round 4
// baseline (speedup 1.0000x reference)
#include <cuda_runtime.h>
#include <cuda_fp16.h>
#include <cstdint>

#define DEVFN static __device__ __forceinline__

namespace edk {

constexpr int NB = 2, NN = 512, NE = 128, NH = 256;
constexpr int JT = 128, NT = NN / JT;

constexpr int AP = 528;  // padded row stride in bytes (264 halves): conflict-free ldmatrix

// dynamic smem layout
constexpr uint32_t MS_PB  = 0;      // 256 f32
constexpr uint32_t MS_W1D = 1024;   // 256 f32
constexpr uint32_t MS_B2  = 2048;   // 256 f32
constexpr uint32_t MS_W3  = 3072;   // 256 f32
constexpr uint32_t MS_D   = 4096;   // 128 f32
constexpr uint32_t MS_HI  = 4608;   // 128 fp16 (256B)
constexpr uint32_t MS_RED = 4864;   // 128 f32
constexpr uint32_t SMA    = 8192;               // A tile: 128 rows x 528B = 67584
constexpr uint32_t SMB    = SMA + 128 * AP;     // B tile: 256 rows x 528B = 135168
constexpr uint32_t SMEM_TOTAL = SMB + 256 * AP; // 210944

// ---- device scratch ----
__device__ __align__(16) __half g_hf16[NB * NN * NE];
__device__ __align__(16) __half g_B1f16[NH * NH];   // [k][n]: k<128 -> W1[256+k][n] (habs), else W1[k][n] (hj)
__device__ __align__(16) __half g_W2f16[NH * NH];   // [k][n] = W2[k][n]
__device__ float g_PB[NB * NN * NH];                // h_i . W1a + b1 (fp32 exact)
__device__ float g_raw[NB * NN * NN];

// ---- helpers ----
DEVFN uint32_t smem_u32(const void* p) {
    uint32_t a;
    asm("{ .reg .u64 t; cvta.to.shared.u64 t, %1; cvt.u32.u64 %0, t; }" : "=r"(a) : "l"(p));
    return a;
}
DEVFN void cp16(uint32_t dst, const void* src) {
    asm volatile("cp.async.cg.shared.global [%0], [%1], 16;" :: "r"(dst), "l"(src) : "memory");
}
DEVFN void cp_commit() { asm volatile("cp.async.commit_group;" ::: "memory"); }
DEVFN void cp_wait0()  { asm volatile("cp.async.wait_group 0;" ::: "memory"); }

DEVFN void ldm_x4(uint32_t* r, uint32_t addr) {
    asm volatile("ldmatrix.sync.aligned.m8n8.x4.shared.b16 {%0,%1,%2,%3}, [%4];"
                 : "=r"(r[0]), "=r"(r[1]), "=r"(r[2]), "=r"(r[3]) : "r"(addr));
}
DEVFN void ldm_x4_t(uint32_t* r, uint32_t addr) {
    asm volatile("ldmatrix.sync.aligned.m8n8.x4.trans.shared.b16 {%0,%1,%2,%3}, [%4];"
                 : "=r"(r[0]), "=r"(r[1]), "=r"(r[2]), "=r"(r[3]) : "r"(addr));
}
DEVFN void mma16816(float* d, const uint32_t* a, const uint32_t* b) {
    asm volatile(
        "mma.sync.aligned.m16n8k16.row.col.f32.f16.f16.f32 "
        "{%0,%1,%2,%3}, {%4,%5,%6,%7}, {%8,%9}, {%0,%1,%2,%3};"
        : "+f"(d[0]), "+f"(d[1]), "+f"(d[2]), "+f"(d[3])
        : "r"(a[0]), "r"(a[1]), "r"(a[2]), "r"(a[3]), "r"(b[0]), "r"(b[1]));
}

// GEMM: M=128 x N=256 x K=256, warp tile 64m x 64n (warp grid 2x4), 8 warps.
// A0/B0 include per-lane ldmatrix address components.
DEVFN void gemm_256(uint32_t A0, uint32_t B0, float (&acc)[4][8][4]) {
#pragma unroll 2
    for (int kk = 0; kk < 16; kk++) {
        uint32_t a[4][4], bf[4][4];
#pragma unroll
        for (int tm = 0; tm < 4; tm++) ldm_x4(a[tm], A0 + tm * (16 * AP) + kk * 32);
#pragma unroll
        for (int tn = 0; tn < 4; tn++) ldm_x4_t(bf[tn], B0 + kk * (16 * AP) + tn * 32);
#pragma unroll
        for (int tm = 0; tm < 4; tm++)
#pragma unroll
            for (int tn = 0; tn < 8; tn++)
                mma16816(acc[tm][tn], a[tm], &bf[tn >> 1][(tn & 1) * 2]);
    }
}

// ---- prep kernels ----
__global__ void prep_hf16(const float* __restrict__ node) {
    int idx = blockIdx.x * 256 + threadIdx.x;
    if (idx < NB * NN * NE) g_hf16[idx] = __float2half_rn(node[idx]);
}
__global__ void prep_B1(const float* __restrict__ W1) {
    int idx = blockIdx.x * 256 + threadIdx.x;  // 65536
    int k = idx >> 8, n = idx & 255;
    float v = (k < 128) ? W1[(256 + k) * NH + n] : W1[k * NH + n];
    g_B1f16[idx] = __float2half_rn(v);
}
__global__ void prep_W2(const float* __restrict__ W2) {
    int idx = blockIdx.x * 256 + threadIdx.x;
    g_W2f16[idx] = __float2half_rn(W2[idx]);
}
__global__ void prep_PB(const float* __restrict__ node, const float* __restrict__ W1,
                        const float* __restrict__ b1) {
    __shared__ float row[NE];
    int bi = blockIdx.x, h = threadIdx.x;
    if (h < NE) row[h] = node[bi * NE + h];
    __syncthreads();
    float acc = b1[h];
#pragma unroll 16
    for (int k = 0; k < NE; k++) acc = fmaf(row[k], W1[k * NH + h], acc);
    g_PB[bi * NH + h] = acc;
}

// ---- main fused kernel: one CTA = (b, i, j-tile of 128), 256 threads ----
__global__ void __launch_bounds__(256, 1)
main_kernel(const float* __restrict__ euclid, const float* __restrict__ W1,
            const float* __restrict__ b2, const float* __restrict__ W3,
            const float* __restrict__ b3) {
    extern __shared__ char smem[];
    uint32_t sb = smem_u32(smem);
    int tid = threadIdx.x, wid = tid >> 5, lane = tid & 31;
    int cta = blockIdx.x;
    int jt = cta & (NT - 1);
    int bi = cta >> 2;           // b*512 + i
    int b  = bi >> 9;
    int i  = bi & 511;
    int j0 = jt * JT;

    // kick B1 load (gmem [k][n] rows of 512B -> padded smem rows of 528B)
    {
        const char* src = (const char*)g_B1f16;
#pragma unroll
        for (int it = 0; it < 32; it++) {
            int id = tid + it * 256;
            int r = id >> 5, c = id & 31;
            cp16(sb + SMB + r * AP + c * 16, src + r * 512 + c * 16);
        }
        cp_commit();
    }
    // small per-CTA vectors
    {
        int c = tid;
        if (c < 256) {
            ((float*)(smem + MS_PB))[c]  = g_PB[bi * NH + c];
            ((float*)(smem + MS_W1D))[c] = W1[384 * NH + c];
            ((float*)(smem + MS_B2))[c]  = b2[c];
            ((float*)(smem + MS_W3))[c]  = W3[c];
        }
        if (tid < 128) {
            ((float*)(smem + MS_D))[tid]   = euclid[(size_t)bi * NN + j0 + tid];
            ((float*)(smem + MS_RED))[tid] = 0.0f;
        }
        if (tid < 64)
            ((uint32_t*)(smem + MS_HI))[tid] =
                ((const uint32_t*)(g_hf16 + (size_t)(b * NN + i) * NE))[tid];
    }
    __syncthreads();

    // build A1: row r, cols [0,128)=|h_i-h_j| fp16, cols [128,256)=h_j
    {
        int r = tid >> 1, hh = tid & 1;  // half-row: 64 halves
        const uint4* hj  = (const uint4*)(g_hf16 + (size_t)(b * NN + j0 + r) * NE + hh * 64);
        const uint4* hip = (const uint4*)(smem + MS_HI) + hh * 8;
        char* A = smem + SMA + r * AP;
#pragma unroll
        for (int u = 0; u < 8; u++) {
            uint4 jv = hj[u], iv = hip[u], ab;
            const __half2* jp = (const __half2*)&jv;
            const __half2* ip = (const __half2*)&iv;
            __half2* ap = (__half2*)&ab;
#pragma unroll
            for (int e = 0; e < 4; e++) ap[e] = __habs2(__hsub2(ip[e], jp[e]));
            *(uint4*)(A + (hh * 64 + u * 8) * 2)       = ab;
            *(uint4*)(A + (128 + hh * 64 + u * 8) * 2) = jv;
        }
    }
    cp_wait0();
    __syncthreads();

    int mb = (wid & 1) * 64, nb = (wid >> 1) * 64;
    int g = lane >> 2, t4 = lane & 3;
    // per-lane ldmatrix address bases
    uint32_t A0 = sb + SMA + (mb + (lane & 15)) * AP + (lane >> 4) * 16;
    uint32_t B0 = sb + SMB + (lane & 15) * AP + nb * 2 + (lane >> 4) * 16;

    float acc[4][8][4];
#pragma unroll
    for (int x = 0; x < 4; x++)
#pragma unroll
        for (int y = 0; y < 8; y++)
#pragma unroll
            for (int z = 0; z < 4; z++) acc[x][y][z] = 0.0f;

    // ---- GEMM1 ----
    gemm_256(A0, B0, acc);
    __syncthreads();  // all reads of A1/B1 done

    // kick W2 load (overlaps epilogue1)
    {
        const char* src = (const char*)g_W2f16;
#pragma unroll
        for (int it = 0; it < 32; it++) {
            int id = tid + it * 256;
            int r = id >> 5, c = id & 31;
            cp16(sb + SMB + r * AP + c * 16, src + r * 512 + c * 16);
        }
        cp_commit();
    }

    // ---- Epilogue 1: + PB + d*w1d, relu, fp16 -> A buffer (A2) ----
    {
        const float* PBs  = (const float*)(smem + MS_PB);
        const float* w1ds = (const float*)(smem + MS_W1D);
        const float* ds   = (const float*)(smem + MS_D);
#pragma unroll
        for (int tm = 0; tm < 4; tm++) {
            int r0 = mb + tm * 16 + g;
            float d0 = ds[r0], d1 = ds[r0 + 8];
            char* rp0 = smem + SMA + r0 * AP;
            char* rp1 = rp0 + 8 * AP;
#pragma unroll
            for (int tn = 0; tn < 8; tn++) {
                int c = nb + tn * 8 + t4 * 2;
                float pb0 = PBs[c], pb1 = PBs[c + 1];
                float w0 = w1ds[c], w1v = w1ds[c + 1];
                float v0 = fmaxf(fmaf(d0, w0,  acc[tm][tn][0] + pb0), 0.0f);
                float v1 = fmaxf(fmaf(d0, w1v, acc[tm][tn][1] + pb1), 0.0f);
                float v2 = fmaxf(fmaf(d1, w0,  acc[tm][tn][2] + pb0), 0.0f);
                float v3 = fmaxf(fmaf(d1, w1v, acc[tm][tn][3] + pb1), 0.0f);
                *(__half2*)(rp0 + c * 2) = __floats2half2_rn(v0, v1);
                *(__half2*)(rp1 + c * 2) = __floats2half2_rn(v2, v3);
            }
        }
    }
    cp_wait0();
    __syncthreads();

#pragma unroll
    for (int x = 0; x < 4; x++)
#pragma unroll
        for (int y = 0; y < 8; y++)
#pragma unroll
            for (int z = 0; z < 4; z++) acc[x][y][z] = 0.0f;

    // ---- GEMM2 ----
    gemm_256(A0, B0, acc);

    // ---- Epilogue 2: relu(+b2) . W3, reduce, + b3 ----
    {
        const float* b2s = (const float*)(smem + MS_B2);
        const float* w3s = (const float*)(smem + MS_W3);
        float s[4][2];
#pragma unroll
        for (int tm = 0; tm < 4; tm++) { s[tm][0] = 0.0f; s[tm][1] = 0.0f; }
#pragma unroll
        for (int tm = 0; tm < 4; tm++)
#pragma unroll
            for (int tn = 0; tn < 8; tn++) {
                int c = nb + tn * 8 + t4 * 2;
                float bb0 = b2s[c], bb1 = b2s[c + 1];
                float w0 = w3s[c], w1v = w3s[c + 1];
                s[tm][0] = fmaf(fmaxf(acc[tm][tn][0] + bb0, 0.0f), w0,
                           fmaf(fmaxf(acc[tm][tn][1] + bb1, 0.0f), w1v, s[tm][0]));
                s[tm][1] = fmaf(fmaxf(acc[tm][tn][2] + bb0, 0.0f), w0,
                           fmaf(fmaxf(acc[tm][tn][3] + bb1, 0.0f), w1v, s[tm][1]));
            }
        float* red = (float*)(smem + MS_RED);
#pragma unroll
        for (int tm = 0; tm < 4; tm++)
#pragma unroll
            for (int h = 0; h < 2; h++) {
                float v = s[tm][h];
                v += __shfl_xor_sync(0xffffffffu, v, 1);
                v += __shfl_xor_sync(0xffffffffu, v, 2);
                if (t4 == 0) atomicAdd(red + mb + tm * 16 + g + h * 8, v);
            }
    }
    __syncthreads();
    if (tid < 128)
        g_raw[(size_t)bi * NN + j0 + tid] = ((const float*)(smem + MS_RED))[tid] + b3[0];
}

// ---- symmetrize + zero diagonal ----
__global__ void sym_kernel(float* __restrict__ out) {
    int idx = blockIdx.x * 256 + threadIdx.x;  // 524288
    int bb = idx >> 18;
    int rem = idx & (NN * NN - 1);
    int i = rem >> 9, j = rem & 511;
    float v = (i == j) ? 0.0f
                       : 0.5f * (g_raw[idx] + g_raw[(bb << 18) + (j << 9) + i]);
    out[idx] = v;
}

}  // namespace edk

extern "C" void kernel_launch(void* const* d_in, const int* in_sizes, int n_in,
                              void* d_out, int out_size) {
    (void)in_sizes; (void)n_in; (void)out_size;
    using namespace edk;
    const float* node   = (const float*)d_in[0];
    // d_in[1] = problems (unused; euclid matrix provided)
    const float* euclid = (const float*)d_in[2];
    const float* W1 = (const float*)d_in[3];
    const float* b1 = (const float*)d_in[4];
    const float* W2 = (const float*)d_in[5];
    const float* b2 = (const float*)d_in[6];
    const float* W3 = (const float*)d_in[7];
    const float* b3 = (const float*)d_in[8];
    float* out = (float*)d_out;

    cudaFuncSetAttribute(main_kernel, cudaFuncAttributeMaxDynamicSharedMemorySize, SMEM_TOTAL);

    prep_hf16<<<512, 256>>>(node);
    prep_B1<<<256, 256>>>(W1);
    prep_W2<<<256, 256>>>(W2);
    prep_PB<<<NB * NN, 256>>>(node, W1, b1);
    main_kernel<<<NB * NN * NT, 256, SMEM_TOTAL>>>(euclid, W1, b2, W3, b3);
    sym_kernel<<<2048, 256>>>(out);
}